// round 1
// baseline (speedup 1.0000x reference)
#include <cuda_runtime.h>

#define N_NODES_MAX 50000
#define E_MAX       800000
#define NF          128
#define NC          40

// ---------------- scratch (static device globals; no allocation) ----------------
__device__ int   g_src[E_MAX];
__device__ int   g_dst[E_MAX];
__device__ int   g_col[E_MAX];
__device__ int   g_deg[N_NODES_MAX];
__device__ int   g_rowptr[N_NODES_MAX + 1];
__device__ int   g_cursor[N_NODES_MAX];
__device__ float g_dinv[N_NODES_MAX];
__device__ __align__(16) float g_hs[N_NODES_MAX * NF];
__device__ __align__(16) float g_a [N_NODES_MAX * NF];
__device__ int   g_flag64;

// ---------------- CSR build ----------------
__global__ void k_zero(int n) {
    int i = blockIdx.x * blockDim.x + threadIdx.x;
    if (i < n) g_deg[i] = 0;
}

// Detect int64 vs int32 edge_index: if int64, every odd 32-bit word (high half)
// is zero (values in [0, 50000)). For int32, 32 random indices all-zero is
// impossible in practice.
__global__ void k_detect(const unsigned int* __restrict__ ei_words) {
    unsigned v = ei_words[2 * threadIdx.x + 1];
    unsigned mask = __ballot_sync(0xffffffffu, v != 0u);
    if (threadIdx.x == 0) g_flag64 = (mask == 0u) ? 1 : 0;
}

__global__ void k_decode(const void* __restrict__ ei, int E) {
    int e = blockIdx.x * blockDim.x + threadIdx.x;
    if (e >= E) return;
    int s, d;
    if (g_flag64) {
        const long long* p = (const long long*)ei;
        s = (int)p[e]; d = (int)p[E + e];
    } else {
        const int* p = (const int*)ei;
        s = p[e]; d = p[E + e];
    }
    g_src[e] = s;
    g_dst[e] = d;
    atomicAdd(&g_deg[d], 1);
}

// Single-block exclusive scan over degrees -> row_ptr, cursor, dinv.
__global__ void k_scan(int n) {
    __shared__ int sh[1024];
    int t = threadIdx.x;
    int carry = 0;
    for (int base = 0; base < n; base += 1024) {
        int i = base + t;
        int v = (i < n) ? g_deg[i] : 0;
        sh[t] = v;
        __syncthreads();
        for (int off = 1; off < 1024; off <<= 1) {
            int a = (t >= off) ? sh[t - off] : 0;
            __syncthreads();
            sh[t] += a;
            __syncthreads();
        }
        int incl = sh[t];
        if (i < n) {
            int excl = carry + incl - v;
            g_rowptr[i] = excl;
            g_cursor[i] = excl;
            g_dinv[i]   = rsqrtf(1.0f + (float)v);
        }
        carry += sh[1023];
        __syncthreads();
    }
    if (t == 0) g_rowptr[n] = carry;
}

__global__ void k_scatter(int E) {
    int e = blockIdx.x * blockDim.x + threadIdx.x;
    if (e >= E) return;
    int d = g_dst[e];
    int p = atomicAdd(&g_cursor[d], 1);
    g_col[p] = g_src[e];
}

// ---------------- GEMM: out[row] = dinv[row] * (X[row] @ W), X:[n,128], W:[128,128]
// 256 threads = 8 warps; warp computes 8 rows x 128 cols; 64 rows per block.
#define G_ROWS_PER_WARP 8
#define G_WARPS 8
#define G_ROWS (G_ROWS_PER_WARP * G_WARPS)

__global__ void k_gemm(const float* __restrict__ Xext,
                       const float* __restrict__ W,
                       int use_internal, int n) {
    extern __shared__ float sh[];
    float* Ws = sh;                 // 128*128 floats
    float* Xs = sh + NF * NF;       // 64*128 floats
    const float* X = use_internal ? (const float*)g_a : Xext;

    int t = threadIdx.x;
    int lane = t & 31;
    int w = t >> 5;
    int row0 = blockIdx.x * G_ROWS;

    float4* Ws4 = (float4*)Ws;
    const float4* W4 = (const float4*)W;
    #pragma unroll
    for (int i = t; i < NF * NF / 4; i += 256) Ws4[i] = W4[i];

    float4* Xs4 = (float4*)Xs;
    const float4* X4 = (const float4*)X;
    for (int i = t; i < G_ROWS * NF / 4; i += 256) {
        int r  = i >> 5;    // / 32 float4 per row
        int rc = i & 31;
        int gr = row0 + r;
        Xs4[i] = (gr < n) ? X4[gr * 32 + rc] : make_float4(0.f, 0.f, 0.f, 0.f);
    }
    __syncthreads();

    int wr = w * G_ROWS_PER_WARP;
    float4 acc[G_ROWS_PER_WARP];
    #pragma unroll
    for (int r = 0; r < G_ROWS_PER_WARP; r++) acc[r] = make_float4(0.f, 0.f, 0.f, 0.f);

    #pragma unroll 4
    for (int k4 = 0; k4 < NF / 4; k4++) {
        float4 w0 = Ws4[(k4 * 4 + 0) * 32 + lane];
        float4 w1 = Ws4[(k4 * 4 + 1) * 32 + lane];
        float4 w2 = Ws4[(k4 * 4 + 2) * 32 + lane];
        float4 w3 = Ws4[(k4 * 4 + 3) * 32 + lane];
        #pragma unroll
        for (int r = 0; r < G_ROWS_PER_WARP; r++) {
            float4 xq = Xs4[(wr + r) * 32 + k4];
            acc[r].x += xq.x * w0.x; acc[r].y += xq.x * w0.y;
            acc[r].z += xq.x * w0.z; acc[r].w += xq.x * w0.w;
            acc[r].x += xq.y * w1.x; acc[r].y += xq.y * w1.y;
            acc[r].z += xq.y * w1.z; acc[r].w += xq.y * w1.w;
            acc[r].x += xq.z * w2.x; acc[r].y += xq.z * w2.y;
            acc[r].z += xq.z * w2.z; acc[r].w += xq.z * w2.w;
            acc[r].x += xq.w * w3.x; acc[r].y += xq.w * w3.y;
            acc[r].z += xq.w * w3.z; acc[r].w += xq.w * w3.w;
        }
    }

    float4* out4 = (float4*)g_hs;
    #pragma unroll
    for (int r = 0; r < G_ROWS_PER_WARP; r++) {
        int gr = row0 + wr + r;
        if (gr < n) {
            float di = g_dinv[gr];
            float4 o;
            o.x = acc[r].x * di; o.y = acc[r].y * di;
            o.z = acc[r].z * di; o.w = acc[r].w * di;
            out4[gr * 32 + lane] = o;
        }
    }
}

// ---------------- Aggregation: warp per dst node ----------------
// out[i] = (relu?) dinv[i]*(hs[i] + sum_{e: dst=i} hs[col[e]]) + bias
__global__ void k_agg(const float* __restrict__ bias, int n, int do_relu) {
    int gw = (blockIdx.x * blockDim.x + threadIdx.x) >> 5;
    int lane = threadIdx.x & 31;
    if (gw >= n) return;

    const float4* hs4 = (const float4*)g_hs;
    float4 acc = hs4[gw * 32 + lane];

    int s = g_rowptr[gw];
    int e = g_rowptr[gw + 1];
    for (int b = s; b < e; b += 32) {
        int idx = (b + lane < e) ? g_col[b + lane] : 0;
        int cnt = min(32, e - b);
        int j = 0;
        for (; j + 4 <= cnt; j += 4) {
            int s0 = __shfl_sync(0xffffffffu, idx, j);
            int s1 = __shfl_sync(0xffffffffu, idx, j + 1);
            int s2 = __shfl_sync(0xffffffffu, idx, j + 2);
            int s3 = __shfl_sync(0xffffffffu, idx, j + 3);
            float4 v0 = hs4[s0 * 32 + lane];
            float4 v1 = hs4[s1 * 32 + lane];
            float4 v2 = hs4[s2 * 32 + lane];
            float4 v3 = hs4[s3 * 32 + lane];
            acc.x += (v0.x + v1.x) + (v2.x + v3.x);
            acc.y += (v0.y + v1.y) + (v2.y + v3.y);
            acc.z += (v0.z + v1.z) + (v2.z + v3.z);
            acc.w += (v0.w + v1.w) + (v2.w + v3.w);
        }
        for (; j < cnt; j++) {
            int sj = __shfl_sync(0xffffffffu, idx, j);
            float4 v = hs4[sj * 32 + lane];
            acc.x += v.x; acc.y += v.y; acc.z += v.z; acc.w += v.w;
        }
    }

    float di = g_dinv[gw];
    float4 bb = ((const float4*)bias)[lane];
    float4 o;
    o.x = di * acc.x + bb.x;
    o.y = di * acc.y + bb.y;
    o.z = di * acc.z + bb.z;
    o.w = di * acc.w + bb.w;
    if (do_relu) {
        o.x = fmaxf(o.x, 0.f); o.y = fmaxf(o.y, 0.f);
        o.z = fmaxf(o.z, 0.f); o.w = fmaxf(o.w, 0.f);
    }
    ((float4*)g_a)[gw * 32 + lane] = o;
}

// ---------------- Final: out = log_softmax(A @ Wout + bout), thread per row ----------------
__global__ void k_final(const float* __restrict__ Wout,
                        const float* __restrict__ bout,
                        float* __restrict__ out, int n) {
    __shared__ float Ws[NF * NC];    // 20 KB
    __shared__ float bs[NC];
    int t = threadIdx.x;
    for (int i = t; i < NF * NC; i += blockDim.x) Ws[i] = Wout[i];
    if (t < NC) bs[t] = bout[t];
    __syncthreads();

    int row = blockIdx.x * blockDim.x + t;
    if (row >= n) return;

    float acc[NC];
    #pragma unroll
    for (int c = 0; c < NC; c++) acc[c] = bs[c];

    const float4* A4  = (const float4*)g_a;
    const float4* Ws4 = (const float4*)Ws;
    for (int k4 = 0; k4 < NF / 4; k4++) {
        float4 xv = A4[row * 32 + k4];
        #pragma unroll
        for (int c4 = 0; c4 < NC / 4; c4++) {
            float4 w0 = Ws4[(k4 * 4 + 0) * (NC / 4) + c4];
            float4 w1 = Ws4[(k4 * 4 + 1) * (NC / 4) + c4];
            float4 w2 = Ws4[(k4 * 4 + 2) * (NC / 4) + c4];
            float4 w3 = Ws4[(k4 * 4 + 3) * (NC / 4) + c4];
            acc[c4 * 4 + 0] += xv.x * w0.x + xv.y * w1.x + xv.z * w2.x + xv.w * w3.x;
            acc[c4 * 4 + 1] += xv.x * w0.y + xv.y * w1.y + xv.z * w2.y + xv.w * w3.y;
            acc[c4 * 4 + 2] += xv.x * w0.z + xv.y * w1.z + xv.z * w2.z + xv.w * w3.z;
            acc[c4 * 4 + 3] += xv.x * w0.w + xv.y * w1.w + xv.z * w2.w + xv.w * w3.w;
        }
    }

    float m = acc[0];
    #pragma unroll
    for (int c = 1; c < NC; c++) m = fmaxf(m, acc[c]);
    float ssum = 0.f;
    #pragma unroll
    for (int c = 0; c < NC; c++) ssum += __expf(acc[c] - m);
    float ls = m + __logf(ssum);
    #pragma unroll
    for (int c = 0; c < NC; c++) out[row * NC + c] = acc[c] - ls;
}

// ---------------- launch ----------------
extern "C" void kernel_launch(void* const* d_in, const int* in_sizes, int n_in,
                              void* d_out, int out_size) {
    const float* x    = (const float*)d_in[0];
    const void*  ei   = d_in[1];
    const float* Win  = (const float*)d_in[2];
    const float* bin  = (const float*)d_in[3];
    const float* W1   = (const float*)d_in[4];
    const float* b1   = (const float*)d_in[5];
    const float* Wout = (const float*)d_in[6];
    const float* bout = (const float*)d_in[7];
    float* out = (float*)d_out;

    int n = in_sizes[0] / NF;       // 50000
    int E = in_sizes[1] / 2;        // 800000

    size_t gemm_smem = (size_t)(NF * NF + G_ROWS * NF) * sizeof(float);  // 96 KB
    cudaFuncSetAttribute(k_gemm, cudaFuncAttributeMaxDynamicSharedMemorySize,
                         (int)gemm_smem);

    // CSR build (every call; no caching allowed)
    k_zero   <<<(n + 255) / 256, 256>>>(n);
    k_detect <<<1, 32>>>((const unsigned int*)ei);
    k_decode <<<(E + 255) / 256, 256>>>(ei, E);
    k_scan   <<<1, 1024>>>(n);
    k_scatter<<<(E + 255) / 256, 256>>>(E);

    int gemm_blocks = (n + G_ROWS - 1) / G_ROWS;
    int agg_blocks  = (n * 32 + 255) / 256;

    // layer 1: h1 = gcn_conv(x, W_in) + b_in
    k_gemm<<<gemm_blocks, 256, gemm_smem>>>(x, Win, 0, n);
    k_agg <<<agg_blocks, 256>>>(bin, n, 0);
    // layer 2: h2 = relu(gcn_conv(h1, W1) + b1)
    k_gemm<<<gemm_blocks, 256, gemm_smem>>>(nullptr, W1, 1, n);
    k_agg <<<agg_blocks, 256>>>(b1, n, 1);
    // output layer + log_softmax
    k_final<<<(n + 255) / 256, 256>>>(Wout, bout, out, n);
}

// round 2
// speedup vs baseline: 1.2915x; 1.2915x over previous
#include <cuda_runtime.h>

#define N_NODES_MAX 50000
#define E_MAX       800000
#define NF          128
#define NC          40
#define SCAN_TILE   1024
#define NB_MAX      ((N_NODES_MAX + SCAN_TILE - 1) / SCAN_TILE)   // 49

// ---------------- scratch (static device globals; no allocation) ----------------
__device__ int   g_src[E_MAX];
__device__ int   g_dst[E_MAX];
__device__ int   g_pos[E_MAX];
__device__ int   g_col[E_MAX];
__device__ int   g_deg[N_NODES_MAX];
__device__ int   g_rowptr[N_NODES_MAX + 1];
__device__ int   g_bsum[NB_MAX];
__device__ int   g_boff[NB_MAX];
__device__ float g_dinv[N_NODES_MAX];
__device__ __align__(16) float g_hs[N_NODES_MAX * NF];
__device__ __align__(16) float g_a [N_NODES_MAX * NF];
__device__ int   g_flag64;

// ---------------- CSR build ----------------
__global__ void k_zero(int n) {
    int i = blockIdx.x * blockDim.x + threadIdx.x;
    if (i < n) g_deg[i] = 0;
}

// Detect int64 vs int32 edge_index: if int64, every odd 32-bit word (high half)
// is zero (values in [0, 50000)).
__global__ void k_detect(const unsigned int* __restrict__ ei_words) {
    unsigned v = ei_words[2 * threadIdx.x + 1];
    unsigned mask = __ballot_sync(0xffffffffu, v != 0u);
    if (threadIdx.x == 0) g_flag64 = (mask == 0u) ? 1 : 0;
}

// Decode edges; histogram degrees; remember within-bucket slot for atomic-free scatter.
__global__ void k_decode(const void* __restrict__ ei, int E) {
    int e = blockIdx.x * blockDim.x + threadIdx.x;
    if (e >= E) return;
    int s, d;
    if (g_flag64) {
        const long long* p = (const long long*)ei;
        s = (int)p[e]; d = (int)p[E + e];
    } else {
        const int* p = (const int*)ei;
        s = p[e]; d = p[E + e];
    }
    g_src[e] = s;
    g_dst[e] = d;
    g_pos[e] = atomicAdd(&g_deg[d], 1);
}

// Multi-block scan, phase 1: per-tile exclusive scan via warp shuffles.
__global__ void k_scan1(int n) {
    __shared__ int warpsum[32];
    int b = blockIdx.x;
    int i = b * SCAN_TILE + threadIdx.x;
    int lane = threadIdx.x & 31;
    int w    = threadIdx.x >> 5;
    int v = (i < n) ? g_deg[i] : 0;

    int incl = v;
    #pragma unroll
    for (int off = 1; off < 32; off <<= 1) {
        int t = __shfl_up_sync(0xffffffffu, incl, off);
        if (lane >= off) incl += t;
    }
    if (lane == 31) warpsum[w] = incl;
    __syncthreads();
    if (w == 0) {
        int s = warpsum[lane];
        #pragma unroll
        for (int off = 1; off < 32; off <<= 1) {
            int t = __shfl_up_sync(0xffffffffu, s, off);
            if (lane >= off) s += t;
        }
        warpsum[lane] = s;
    }
    __syncthreads();
    int excl = incl - v + (w > 0 ? warpsum[w - 1] : 0);
    if (i < n) {
        g_rowptr[i] = excl;
        g_dinv[i]   = rsqrtf(1.0f + (float)v);
    }
    if (threadIdx.x == 0) g_bsum[b] = warpsum[31];
}

// Phase 2: scan the 49 block sums (single small block).
__global__ void k_scan2(int nb, int n) {
    __shared__ int sh[64];
    int t = threadIdx.x;                  // 64 threads
    int v = (t < nb) ? g_bsum[t] : 0;
    sh[t] = v;
    __syncthreads();
    #pragma unroll
    for (int off = 1; off < 64; off <<= 1) {
        int a = (t >= off) ? sh[t - off] : 0;
        __syncthreads();
        sh[t] += a;
        __syncthreads();
    }
    if (t < nb) g_boff[t] = sh[t] - v;
    if (t == 63) g_rowptr[n] = sh[63];
}

// Phase 3: add block offsets.
__global__ void k_scan3(int n) {
    int i = blockIdx.x * SCAN_TILE + threadIdx.x;
    if (i < n) g_rowptr[i] += g_boff[blockIdx.x];
}

// Atomic-free scatter using precomputed within-bucket slots.
__global__ void k_scatter(int E) {
    int e = blockIdx.x * blockDim.x + threadIdx.x;
    if (e >= E) return;
    int d = g_dst[e];
    g_col[g_rowptr[d] + g_pos[e]] = g_src[e];
}

// ---------------- GEMM: out[row] = dinv[row] * (X[row] @ W) ----------------
#define G_ROWS_PER_WARP 8
#define G_WARPS 8
#define G_ROWS (G_ROWS_PER_WARP * G_WARPS)

__global__ void k_gemm(const float* __restrict__ Xext,
                       const float* __restrict__ W,
                       int use_internal, int n) {
    extern __shared__ float sh[];
    float* Ws = sh;                 // 128*128 floats
    float* Xs = sh + NF * NF;       // 64*128 floats
    const float* X = use_internal ? (const float*)g_a : Xext;

    int t = threadIdx.x;
    int lane = t & 31;
    int w = t >> 5;
    int row0 = blockIdx.x * G_ROWS;

    float4* Ws4 = (float4*)Ws;
    const float4* W4 = (const float4*)W;
    #pragma unroll
    for (int i = t; i < NF * NF / 4; i += 256) Ws4[i] = W4[i];

    float4* Xs4 = (float4*)Xs;
    const float4* X4 = (const float4*)X;
    for (int i = t; i < G_ROWS * NF / 4; i += 256) {
        int r  = i >> 5;
        int rc = i & 31;
        int gr = row0 + r;
        Xs4[i] = (gr < n) ? X4[gr * 32 + rc] : make_float4(0.f, 0.f, 0.f, 0.f);
    }
    __syncthreads();

    int wr = w * G_ROWS_PER_WARP;
    float4 acc[G_ROWS_PER_WARP];
    #pragma unroll
    for (int r = 0; r < G_ROWS_PER_WARP; r++) acc[r] = make_float4(0.f, 0.f, 0.f, 0.f);

    #pragma unroll 4
    for (int k4 = 0; k4 < NF / 4; k4++) {
        float4 w0 = Ws4[(k4 * 4 + 0) * 32 + lane];
        float4 w1 = Ws4[(k4 * 4 + 1) * 32 + lane];
        float4 w2 = Ws4[(k4 * 4 + 2) * 32 + lane];
        float4 w3 = Ws4[(k4 * 4 + 3) * 32 + lane];
        #pragma unroll
        for (int r = 0; r < G_ROWS_PER_WARP; r++) {
            float4 xq = Xs4[(wr + r) * 32 + k4];
            acc[r].x += xq.x * w0.x; acc[r].y += xq.x * w0.y;
            acc[r].z += xq.x * w0.z; acc[r].w += xq.x * w0.w;
            acc[r].x += xq.y * w1.x; acc[r].y += xq.y * w1.y;
            acc[r].z += xq.y * w1.z; acc[r].w += xq.y * w1.w;
            acc[r].x += xq.z * w2.x; acc[r].y += xq.z * w2.y;
            acc[r].z += xq.z * w2.z; acc[r].w += xq.z * w2.w;
            acc[r].x += xq.w * w3.x; acc[r].y += xq.w * w3.y;
            acc[r].z += xq.w * w3.z; acc[r].w += xq.w * w3.w;
        }
    }

    float4* out4 = (float4*)g_hs;
    #pragma unroll
    for (int r = 0; r < G_ROWS_PER_WARP; r++) {
        int gr = row0 + wr + r;
        if (gr < n) {
            float di = g_dinv[gr];
            float4 o;
            o.x = acc[r].x * di; o.y = acc[r].y * di;
            o.z = acc[r].z * di; o.w = acc[r].w * di;
            out4[gr * 32 + lane] = o;
        }
    }
}

// ---------------- Aggregation: warp per dst node ----------------
__global__ void k_agg(const float* __restrict__ bias, int n, int do_relu) {
    int gw = (blockIdx.x * blockDim.x + threadIdx.x) >> 5;
    int lane = threadIdx.x & 31;
    if (gw >= n) return;

    const float4* hs4 = (const float4*)g_hs;
    float4 acc = hs4[gw * 32 + lane];

    int s = g_rowptr[gw];
    int e = g_rowptr[gw + 1];
    for (int b = s; b < e; b += 32) {
        int idx = (b + lane < e) ? g_col[b + lane] : 0;
        int cnt = min(32, e - b);
        int j = 0;
        for (; j + 4 <= cnt; j += 4) {
            int s0 = __shfl_sync(0xffffffffu, idx, j);
            int s1 = __shfl_sync(0xffffffffu, idx, j + 1);
            int s2 = __shfl_sync(0xffffffffu, idx, j + 2);
            int s3 = __shfl_sync(0xffffffffu, idx, j + 3);
            float4 v0 = hs4[s0 * 32 + lane];
            float4 v1 = hs4[s1 * 32 + lane];
            float4 v2 = hs4[s2 * 32 + lane];
            float4 v3 = hs4[s3 * 32 + lane];
            acc.x += (v0.x + v1.x) + (v2.x + v3.x);
            acc.y += (v0.y + v1.y) + (v2.y + v3.y);
            acc.z += (v0.z + v1.z) + (v2.z + v3.z);
            acc.w += (v0.w + v1.w) + (v2.w + v3.w);
        }
        for (; j < cnt; j++) {
            int sj = __shfl_sync(0xffffffffu, idx, j);
            float4 v = hs4[sj * 32 + lane];
            acc.x += v.x; acc.y += v.y; acc.z += v.z; acc.w += v.w;
        }
    }

    float di = g_dinv[gw];
    float4 bb = ((const float4*)bias)[lane];
    float4 o;
    o.x = di * acc.x + bb.x;
    o.y = di * acc.y + bb.y;
    o.z = di * acc.z + bb.z;
    o.w = di * acc.w + bb.w;
    if (do_relu) {
        o.x = fmaxf(o.x, 0.f); o.y = fmaxf(o.y, 0.f);
        o.z = fmaxf(o.z, 0.f); o.w = fmaxf(o.w, 0.f);
    }
    ((float4*)g_a)[gw * 32 + lane] = o;
}

// ---------------- Final: out = log_softmax(A @ Wout + bout) ----------------
__global__ void k_final(const float* __restrict__ Wout,
                        const float* __restrict__ bout,
                        float* __restrict__ out, int n) {
    __shared__ float Ws[NF * NC];
    __shared__ float bs[NC];
    int t = threadIdx.x;
    for (int i = t; i < NF * NC; i += blockDim.x) Ws[i] = Wout[i];
    if (t < NC) bs[t] = bout[t];
    __syncthreads();

    int row = blockIdx.x * blockDim.x + t;
    if (row >= n) return;

    float acc[NC];
    #pragma unroll
    for (int c = 0; c < NC; c++) acc[c] = bs[c];

    const float4* A4  = (const float4*)g_a;
    const float4* Ws4 = (const float4*)Ws;
    for (int k4 = 0; k4 < NF / 4; k4++) {
        float4 xv = A4[row * 32 + k4];
        #pragma unroll
        for (int c4 = 0; c4 < NC / 4; c4++) {
            float4 w0 = Ws4[(k4 * 4 + 0) * (NC / 4) + c4];
            float4 w1 = Ws4[(k4 * 4 + 1) * (NC / 4) + c4];
            float4 w2 = Ws4[(k4 * 4 + 2) * (NC / 4) + c4];
            float4 w3 = Ws4[(k4 * 4 + 3) * (NC / 4) + c4];
            acc[c4 * 4 + 0] += xv.x * w0.x + xv.y * w1.x + xv.z * w2.x + xv.w * w3.x;
            acc[c4 * 4 + 1] += xv.x * w0.y + xv.y * w1.y + xv.z * w2.y + xv.w * w3.y;
            acc[c4 * 4 + 2] += xv.x * w0.z + xv.y * w1.z + xv.z * w2.z + xv.w * w3.z;
            acc[c4 * 4 + 3] += xv.x * w0.w + xv.y * w1.w + xv.z * w2.w + xv.w * w3.w;
        }
    }

    float m = acc[0];
    #pragma unroll
    for (int c = 1; c < NC; c++) m = fmaxf(m, acc[c]);
    float ssum = 0.f;
    #pragma unroll
    for (int c = 0; c < NC; c++) ssum += __expf(acc[c] - m);
    float ls = m + __logf(ssum);
    #pragma unroll
    for (int c = 0; c < NC; c++) out[row * NC + c] = acc[c] - ls;
}

// ---------------- launch ----------------
extern "C" void kernel_launch(void* const* d_in, const int* in_sizes, int n_in,
                              void* d_out, int out_size) {
    const float* x    = (const float*)d_in[0];
    const void*  ei   = d_in[1];
    const float* Win  = (const float*)d_in[2];
    const float* bin  = (const float*)d_in[3];
    const float* W1   = (const float*)d_in[4];
    const float* b1   = (const float*)d_in[5];
    const float* Wout = (const float*)d_in[6];
    const float* bout = (const float*)d_in[7];
    float* out = (float*)d_out;

    int n = in_sizes[0] / NF;       // 50000
    int E = in_sizes[1] / 2;        // 800000
    int nb = (n + SCAN_TILE - 1) / SCAN_TILE;

    size_t gemm_smem = (size_t)(NF * NF + G_ROWS * NF) * sizeof(float);  // 96 KB
    cudaFuncSetAttribute(k_gemm, cudaFuncAttributeMaxDynamicSharedMemorySize,
                         (int)gemm_smem);

    // CSR build (every call; no caching allowed)
    k_zero   <<<(n + 255) / 256, 256>>>(n);
    k_detect <<<1, 32>>>((const unsigned int*)ei);
    k_decode <<<(E + 255) / 256, 256>>>(ei, E);
    k_scan1  <<<nb, SCAN_TILE>>>(n);
    k_scan2  <<<1, 64>>>(nb, n);
    k_scan3  <<<nb, SCAN_TILE>>>(n);
    k_scatter<<<(E + 255) / 256, 256>>>(E);

    int gemm_blocks = (n + G_ROWS - 1) / G_ROWS;
    int agg_blocks  = (n * 32 + 255) / 256;

    // layer 1
    k_gemm<<<gemm_blocks, 256, gemm_smem>>>(x, Win, 0, n);
    k_agg <<<agg_blocks, 256>>>(bin, n, 0);
    // layer 2
    k_gemm<<<gemm_blocks, 256, gemm_smem>>>(nullptr, W1, 1, n);
    k_agg <<<agg_blocks, 256>>>(b1, n, 1);
    // output
    k_final<<<(n + 255) / 256, 256>>>(Wout, bout, out, n);
}